// round 1
// baseline (speedup 1.0000x reference)
#include <cuda_runtime.h>
#include <math.h>

// Problem constants
#define NTOK  16384
#define DIN   2048
#define HMID  4096
#define NEXP  64
#define NSHARED 8
#define TOPK  2

// GEMM1 tiling
#define BM 128
#define BN 128
#define BK 16

// Router tiling
#define TM  16
#define BK2 128

// Output layout (flattened concat of the reference tuple)
#define G_OFF  0
#define LW_OFF (NTOK * NSHARED)                 // 131072
#define LI_OFF (LW_OFF + NTOK * TOPK)           // 163840
#define W_OFF  (LI_OFF + NTOK * TOPK)           // 196608

// Scratch: h = gelu(x @ W1 + b1), [NTOK, HMID] fp32 (268 MB, static device array)
__device__ float g_h[(size_t)NTOK * HMID];

typedef unsigned long long ull;

__device__ __forceinline__ void ffma2(ull &d, ull a, ull b) {
    asm("fma.rn.f32x2 %0, %1, %2, %0;" : "+l"(d) : "l"(a), "l"(b));
}
__device__ __forceinline__ ull pack2(float x, float y) {
    ull r; asm("mov.b64 %0, {%1, %2};" : "=l"(r) : "f"(x), "f"(y)); return r;
}
__device__ __forceinline__ float2 unpack2(ull v) {
    float2 f; asm("mov.b64 {%0, %1}, %2;" : "=f"(f.x), "=f"(f.y) : "l"(v)); return f;
}
__device__ __forceinline__ float gelu_exact(float v) {
    return 0.5f * v * (1.0f + erff(v * 0.70710678118654752440f));
}

// ---------------------------------------------------------------------------
// Kernel 1: h = gelu(x @ W1 + b1)
// x: [NTOK, DIN], W1: [DIN, HMID], b1: [HMID]
// 128x128 tile, BK=16, 256 threads, 8x8 per thread, packed f32x2 FMA.
// ---------------------------------------------------------------------------
__global__ void __launch_bounds__(256)
gemm1_gelu_kernel(const float* __restrict__ x,
                  const float* __restrict__ W1,
                  const float* __restrict__ b1) {
    __shared__ float As[2][BK][BM + 4];   // transposed A tile (padded)
    __shared__ float Bs[2][BK][BN];

    const int tid = threadIdx.x;
    const int row0 = blockIdx.y * BM;
    const int col0 = blockIdx.x * BN;

    // A-tile load mapping: 128 rows x 16 k  (2 x float4 per thread)
    const int ar  = tid >> 2;         // 0..63 (+64 second half)
    const int ac4 = (tid & 3) * 4;    // 0,4,8,12
    // B-tile load mapping: 16 k x 128 cols (2 x float4 per thread)
    const int bkr = tid >> 5;         // 0..7 (+8 second half)
    const int bc4 = (tid & 31) * 4;   // 0..124

    // compute mapping
    const int tx = tid & 15;          // col group
    const int ty = tid >> 4;          // row group
    const int rr0 = ty * 8;
    const int cc0 = tx * 8;

    ull acc[8][4];
#pragma unroll
    for (int i = 0; i < 8; i++)
#pragma unroll
        for (int j = 0; j < 4; j++) acc[i][j] = 0ULL;

    // prologue: load tile 0
    {
#pragma unroll
        for (int h = 0; h < 2; h++) {
            int r = ar + h * 64;
            float4 v = *reinterpret_cast<const float4*>(
                &x[(size_t)(row0 + r) * DIN + ac4]);
            As[0][ac4 + 0][r] = v.x; As[0][ac4 + 1][r] = v.y;
            As[0][ac4 + 2][r] = v.z; As[0][ac4 + 3][r] = v.w;
        }
#pragma unroll
        for (int h = 0; h < 2; h++) {
            int kk = bkr + h * 8;
            float4 v = *reinterpret_cast<const float4*>(
                &W1[(size_t)kk * HMID + col0 + bc4]);
            *reinterpret_cast<float4*>(&Bs[0][kk][bc4]) = v;
        }
    }
    __syncthreads();

    const int KT = DIN / BK;  // 128
    for (int kt = 0; kt < KT; kt++) {
        int buf = kt & 1;
        // prefetch next tile into the other buffer
        if (kt + 1 < KT) {
            int k0 = (kt + 1) * BK;
            int nb = buf ^ 1;
#pragma unroll
            for (int h = 0; h < 2; h++) {
                int r = ar + h * 64;
                float4 v = *reinterpret_cast<const float4*>(
                    &x[(size_t)(row0 + r) * DIN + k0 + ac4]);
                As[nb][ac4 + 0][r] = v.x; As[nb][ac4 + 1][r] = v.y;
                As[nb][ac4 + 2][r] = v.z; As[nb][ac4 + 3][r] = v.w;
            }
#pragma unroll
            for (int h = 0; h < 2; h++) {
                int kk = bkr + h * 8;
                float4 v = *reinterpret_cast<const float4*>(
                    &W1[(size_t)(k0 + kk) * HMID + col0 + bc4]);
                *reinterpret_cast<float4*>(&Bs[nb][kk][bc4]) = v;
            }
        }
#pragma unroll
        for (int kk = 0; kk < BK; kk++) {
            float4 a0 = *reinterpret_cast<const float4*>(&As[buf][kk][rr0]);
            float4 a1 = *reinterpret_cast<const float4*>(&As[buf][kk][rr0 + 4]);
            const double* bp = reinterpret_cast<const double*>(&Bs[buf][kk][cc0]);
            ull bb[4];
#pragma unroll
            for (int j = 0; j < 4; j++) {
                double bd = bp[j];
                bb[j] = *reinterpret_cast<ull*>(&bd);
            }
            float av[8] = {a0.x, a0.y, a0.z, a0.w, a1.x, a1.y, a1.z, a1.w};
#pragma unroll
            for (int i = 0; i < 8; i++) {
                ull aa = pack2(av[i], av[i]);
#pragma unroll
                for (int j = 0; j < 4; j++) ffma2(acc[i][j], aa, bb[j]);
            }
        }
        __syncthreads();
    }

    // epilogue: bias + gelu + store
    float bias[8];
#pragma unroll
    for (int j = 0; j < 8; j++) bias[j] = b1[col0 + cc0 + j];

#pragma unroll
    for (int i = 0; i < 8; i++) {
        float outv[8];
#pragma unroll
        for (int j = 0; j < 4; j++) {
            float2 c = unpack2(acc[i][j]);
            outv[2 * j + 0] = gelu_exact(c.x + bias[2 * j + 0]);
            outv[2 * j + 1] = gelu_exact(c.y + bias[2 * j + 1]);
        }
        size_t base = (size_t)(row0 + rr0 + i) * HMID + col0 + cc0;
        *reinterpret_cast<float4*>(&g_h[base])     = make_float4(outv[0], outv[1], outv[2], outv[3]);
        *reinterpret_cast<float4*>(&g_h[base + 4]) = make_float4(outv[4], outv[5], outv[6], outv[7]);
    }
}

// ---------------------------------------------------------------------------
// Kernel 2: logits = h @ W2 + b2, softmax, split shared/local, top-2,
//           write all four outputs.
// One block handles TM=16 tokens; 256 threads.
// thread -> (t = tid>>4, eg = tid&15) owns experts 4*eg..4*eg+3 of token t.
// ---------------------------------------------------------------------------
__global__ void __launch_bounds__(256)
router_kernel(const float* __restrict__ W2,
              const float* __restrict__ b2,
              float* __restrict__ out) {
    __shared__ float hs[TM][BK2];        // 8 KB
    __shared__ float w2s[BK2][NEXP];     // 32 KB
    __shared__ float lg[TM][NEXP];       // 4 KB
    __shared__ float sinv[TM];

    const int tid = threadIdx.x;
    const int tok0 = blockIdx.x * TM;
    const int t  = tid >> 4;
    const int eg = tid & 15;

    float tot0 = 0.f, tot1 = 0.f, tot2 = 0.f, tot3 = 0.f;

    for (int k0 = 0; k0 < HMID; k0 += BK2) {
        // load h tile: 16 x 128 floats = 512 float4, 2 per thread
#pragma unroll
        for (int h = 0; h < 2; h++) {
            int f = tid + 256 * h;
            int tr = f >> 5;
            int kc = (f & 31) << 2;
            float4 v = *reinterpret_cast<const float4*>(
                &g_h[(size_t)(tok0 + tr) * HMID + k0 + kc]);
            *reinterpret_cast<float4*>(&hs[tr][kc]) = v;
        }
        // load W2 tile: 128 x 64 floats = 2048 float4, 8 per thread
#pragma unroll
        for (int h = 0; h < 8; h++) {
            int f = tid + 256 * h;
            int kk = f >> 4;
            int e4 = (f & 15) << 2;
            float4 v = *reinterpret_cast<const float4*>(
                &W2[(size_t)(k0 + kk) * NEXP + e4]);
            *reinterpret_cast<float4*>(&w2s[kk][e4]) = v;
        }
        __syncthreads();

        float c0 = 0.f, c1 = 0.f, c2 = 0.f, c3 = 0.f;  // chunk partials
#pragma unroll 4
        for (int kk = 0; kk < BK2; kk++) {
            float a = hs[t][kk];
            float4 w = *reinterpret_cast<const float4*>(&w2s[kk][eg * 4]);
            c0 = fmaf(a, w.x, c0);
            c1 = fmaf(a, w.y, c1);
            c2 = fmaf(a, w.z, c2);
            c3 = fmaf(a, w.w, c3);
        }
        tot0 += c0; tot1 += c1; tot2 += c2; tot3 += c3;
        __syncthreads();
    }

    // logits -> smem (+ bias)
    lg[t][eg * 4 + 0] = tot0 + b2[eg * 4 + 0];
    lg[t][eg * 4 + 1] = tot1 + b2[eg * 4 + 1];
    lg[t][eg * 4 + 2] = tot2 + b2[eg * 4 + 2];
    lg[t][eg * 4 + 3] = tot3 + b2[eg * 4 + 3];
    __syncthreads();

    // per-token softmax + top-2 (threads 0..15, one token each)
    if (tid < TM) {
        const int tok = tok0 + tid;
        float mx = -1e30f;
#pragma unroll
        for (int e = 0; e < NEXP; e++) mx = fmaxf(mx, lg[tid][e]);
        float s = 0.f;
#pragma unroll
        for (int e = 0; e < NEXP; e++) {
            float ev = expf(lg[tid][e] - mx);
            lg[tid][e] = ev;     // store unnormalized exp back
            s += ev;
        }
        float inv = 1.0f / s;
        sinv[tid] = inv;

        // top-2 over local experts (8..63); strict > => lowest index on ties
        float v1 = -1.0f, v2 = -1.0f;
        int i1 = 0, i2 = 0;
#pragma unroll
        for (int e = NSHARED; e < NEXP; e++) {
            float v = lg[tid][e];
            if (v > v1)      { v2 = v1; i2 = i1; v1 = v; i1 = e; }
            else if (v > v2) { v2 = v;  i2 = e; }
        }
        // shared (global) expert weights
#pragma unroll
        for (int e = 0; e < NSHARED; e++)
            out[G_OFF + (size_t)tok * NSHARED + e] = lg[tid][e] * inv;
        // local top-2 weights + indices (relative to local block)
        out[LW_OFF + (size_t)tok * TOPK + 0] = v1 * inv;
        out[LW_OFF + (size_t)tok * TOPK + 1] = v2 * inv;
        out[LI_OFF + (size_t)tok * TOPK + 0] = (float)(i1 - NSHARED);
        out[LI_OFF + (size_t)tok * TOPK + 1] = (float)(i2 - NSHARED);
    }
    __syncthreads();

    // all threads write full weights matrix (coalesced)
    {
        float inv = sinv[t];
        float4 v = *reinterpret_cast<const float4*>(&lg[t][eg * 4]);
        v.x *= inv; v.y *= inv; v.z *= inv; v.w *= inv;
        *reinterpret_cast<float4*>(
            &out[W_OFF + (size_t)(tok0 + t) * NEXP + eg * 4]) = v;
    }
}

// ---------------------------------------------------------------------------
extern "C" void kernel_launch(void* const* d_in, const int* in_sizes, int n_in,
                              void* d_out, int out_size) {
    const float* x  = (const float*)d_in[0];
    const float* W1 = (const float*)d_in[1];
    const float* b1 = (const float*)d_in[2];
    const float* W2 = (const float*)d_in[3];
    const float* b2 = (const float*)d_in[4];
    float* out = (float*)d_out;

    dim3 g1(HMID / BN, NTOK / BM);   // (32, 128)
    gemm1_gelu_kernel<<<g1, 256>>>(x, W1, b1);

    router_kernel<<<NTOK / TM, 256>>>(W2, b2, out);
}